// round 5
// baseline (speedup 1.0000x reference)
#include <cuda_runtime.h>
#include <cstdint>

#define N_NODES 100000
#define N_EDGES 1600000
#define IN_DIM  128
#define HID     64
#define CONVOUT 124   // 2 * 62
#define SCAN_B  1024
#define NSCANB  ((N_NODES + SCAN_B - 1) / SCAN_B)   // 98

// ---------------- scratch (static device globals; no allocs allowed) ----------
__device__ float g_t   [N_NODES * HID];   // (feat@w1)*norm
__device__ float g_h1  [N_NODES * HID];   // dropout(relu(agg*norm))*norm
__device__ float g_agg2[N_NODES * HID];   // layer-2 aggregate
__device__ float g_h2  [N_NODES * HID];   // final node features
__device__ int   g_deg [N_NODES];
__device__ int   g_cnt [N_NODES];
__device__ float g_norm[N_NODES];
__device__ int   g_rowptr[N_NODES + 1];
__device__ int   g_bsum[NSCANB];
__device__ int   g_boff[NSCANB];
__device__ int   g_csr[N_EDGES];          // src ids grouped by dst
__device__ float g_colsum[HID];
__device__ float g_omean[CONVOUT];

// ---------------- threefry2x32 (20 rounds, JAX-compatible) --------------------
__host__ __device__ __forceinline__ void tf2x32(uint32_t k0, uint32_t k1,
                                                uint32_t& x0, uint32_t& x1) {
    uint32_t ks2 = k0 ^ k1 ^ 0x1BD11BDAu;
#define TF_R(r) { x0 += x1; x1 = (x1 << (r)) | (x1 >> (32 - (r))); x1 ^= x0; }
    x0 += k0; x1 += k1;
    TF_R(13) TF_R(15) TF_R(26) TF_R(6)   x0 += k1;  x1 += ks2 + 1u;
    TF_R(17) TF_R(29) TF_R(16) TF_R(24)  x0 += ks2; x1 += k0  + 2u;
    TF_R(13) TF_R(15) TF_R(26) TF_R(6)   x0 += k0;  x1 += k1  + 3u;
    TF_R(17) TF_R(29) TF_R(16) TF_R(24)  x0 += k1;  x1 += ks2 + 4u;
    TF_R(13) TF_R(15) TF_R(26) TF_R(6)   x0 += ks2; x1 += k0  + 5u;
#undef TF_R
}

__device__ __forceinline__ bool drop_keep(uint32_t k0, uint32_t k1, uint32_t idx) {
    uint32_t x0 = 0u, x1 = idx;
    tf2x32(k0, k1, x0, x1);
    return ((x0 ^ x1) & 0x80000000u) == 0u;
}

// ---------------- graph prep ---------------------------------------------------
__global__ void k_zero() {
    int i = blockIdx.x * blockDim.x + threadIdx.x;
    if (i < N_NODES) { g_deg[i] = 0; g_cnt[i] = 0; }
    if (i < HID) g_colsum[i] = 0.f;
}

__global__ void k_deg(const int* __restrict__ dst) {
    int e = blockIdx.x * blockDim.x + threadIdx.x;
    if (e < N_EDGES) atomicAdd(&g_deg[dst[e]], 1);
}

__global__ void k_scan1() {
    __shared__ int s[SCAN_B];
    int t = threadIdx.x, b = blockIdx.x;
    int i = b * SCAN_B + t;
    int v = (i < N_NODES) ? g_deg[i] : 0;
    s[t] = v;
    __syncthreads();
#pragma unroll
    for (int off = 1; off < SCAN_B; off <<= 1) {
        int add = (t >= off) ? s[t - off] : 0;
        __syncthreads();
        s[t] += add;
        __syncthreads();
    }
    if (i < N_NODES) g_rowptr[i + 1] = s[t];
    if (t == SCAN_B - 1) g_bsum[b] = s[t];
}

__global__ void k_scan2() {
    __shared__ int s[128];
    int t = threadIdx.x;
    int v = (t < NSCANB) ? g_bsum[t] : 0;
    s[t] = v;
    __syncthreads();
#pragma unroll
    for (int off = 1; off < 128; off <<= 1) {
        int add = (t >= off) ? s[t - off] : 0;
        __syncthreads();
        s[t] += add;
        __syncthreads();
    }
    if (t < NSCANB) g_boff[t] = s[t] - v;   // exclusive
}

__global__ void k_scan3() {
    int i = blockIdx.x * blockDim.x + threadIdx.x;
    if (i < N_NODES) {
        g_rowptr[i + 1] += g_boff[i >> 10];
        g_norm[i] = rsqrtf((float)(g_deg[i] + 1));
    }
    if (i == 0) g_rowptr[0] = 0;
}

__global__ void k_fill(const int* __restrict__ src, const int* __restrict__ dst) {
    int e = blockIdx.x * blockDim.x + threadIdx.x;
    if (e >= N_EDGES) return;
    int d = dst[e];
    int ofs = atomicAdd(&g_cnt[d], 1);
    g_csr[g_rowptr[d] + ofs] = src[e];
}

// ---------------- gemm1: g_t = (feat @ w1) * norm -------------------------------
__global__ __launch_bounds__(256) void k_gemm1(const float* __restrict__ feat,
                                               const float* __restrict__ w1) {
    __shared__ float sA[16][132];
    __shared__ float sB[16][64];
    int tid = threadIdx.x;
    int nb  = blockIdx.x * 128;
    int tx  = tid & 15;
    int ty  = tid >> 4;
    float acc[8][4] = {};
#pragma unroll
    for (int kc = 0; kc < 8; kc++) {
#pragma unroll
        for (int l = 0; l < 2; l++) {
            int idx = tid + l * 256;
            int nd  = idx >> 2;
            int kq  = idx & 3;
            int gn  = nb + nd;
            float4 v = make_float4(0.f, 0.f, 0.f, 0.f);
            if (gn < N_NODES)
                v = *reinterpret_cast<const float4*>(&feat[(size_t)gn * IN_DIM + kc * 16 + kq * 4]);
            sA[kq * 4 + 0][nd] = v.x;
            sA[kq * 4 + 1][nd] = v.y;
            sA[kq * 4 + 2][nd] = v.z;
            sA[kq * 4 + 3][nd] = v.w;
        }
        {
            int kk = tid >> 4, c4 = tid & 15;
            float4 v = *reinterpret_cast<const float4*>(&w1[(kc * 16 + kk) * HID + c4 * 4]);
            *reinterpret_cast<float4*>(&sB[kk][c4 * 4]) = v;
        }
        __syncthreads();
#pragma unroll
        for (int kk = 0; kk < 16; kk++) {
            float4 b  = *reinterpret_cast<float4*>(&sB[kk][tx * 4]);
            float4 a0 = *reinterpret_cast<float4*>(&sA[kk][ty * 8]);
            float4 a1 = *reinterpret_cast<float4*>(&sA[kk][ty * 8 + 4]);
            float av[8] = {a0.x, a0.y, a0.z, a0.w, a1.x, a1.y, a1.z, a1.w};
#pragma unroll
            for (int i = 0; i < 8; i++) {
                acc[i][0] = fmaf(av[i], b.x, acc[i][0]);
                acc[i][1] = fmaf(av[i], b.y, acc[i][1]);
                acc[i][2] = fmaf(av[i], b.z, acc[i][2]);
                acc[i][3] = fmaf(av[i], b.w, acc[i][3]);
            }
        }
        __syncthreads();
    }
#pragma unroll
    for (int i = 0; i < 8; i++) {
        int gn = nb + ty * 8 + i;
        if (gn < N_NODES) {
            float nm = g_norm[gn];
            float4 v = make_float4(acc[i][0] * nm, acc[i][1] * nm,
                                   acc[i][2] * nm, acc[i][3] * nm);
            *reinterpret_cast<float4*>(&g_t[(size_t)gn * HID + tx * 4]) = v;
        }
    }
}

// ---------------- gather: warp per dst node, float4, 2 edges / iteration --------
// FIN=1: fused fin1 epilogue (norm, relu, dropout, *norm). FIN=0: raw sum store.
template<int FIN>
__global__ __launch_bounds__(256) void k_gather(const float* __restrict__ sbuf,
                                                float* __restrict__ obuf,
                                                uint32_t k0, uint32_t k1) {
    int w = (blockIdx.x * blockDim.x + threadIdx.x) >> 5;
    if (w >= N_NODES) return;
    int lane = threadIdx.x & 31;
    int half = lane >> 4;          // 0: even edges, 1: odd edges
    int q = lane & 15;             // float4 slot
    int beg = g_rowptr[w], end = g_rowptr[w + 1];
    float4 acc = make_float4(0.f, 0.f, 0.f, 0.f);
    if (half == 0)                 // self loop (rows pre-scaled)
        acc = *reinterpret_cast<const float4*>(&sbuf[(size_t)w * HID + q * 4]);

    int base = beg;
    for (; base + 32 <= end; base += 32) {
        int s = g_csr[base + lane];
#pragma unroll
        for (int t = 0; t < 16; t++) {
            int ss = __shfl_sync(0xffffffffu, s, 2 * t + half);
            float4 v = *reinterpret_cast<const float4*>(&sbuf[(size_t)ss * HID + q * 4]);
            acc.x += v.x; acc.y += v.y; acc.z += v.z; acc.w += v.w;
        }
    }
    int rem = end - base;
    if (rem > 0) {
        int s = (lane < rem) ? g_csr[base + lane] : 0;
        int pairs = rem >> 1;
#pragma unroll 4
        for (int t = 0; t < pairs; t++) {
            int ss = __shfl_sync(0xffffffffu, s, 2 * t + half);
            float4 v = *reinterpret_cast<const float4*>(&sbuf[(size_t)ss * HID + q * 4]);
            acc.x += v.x; acc.y += v.y; acc.z += v.z; acc.w += v.w;
        }
        if (rem & 1) {
            int ss = __shfl_sync(0xffffffffu, s, rem - 1);
            if (half == 0) {
                float4 v = *reinterpret_cast<const float4*>(&sbuf[(size_t)ss * HID + q * 4]);
                acc.x += v.x; acc.y += v.y; acc.z += v.z; acc.w += v.w;
            }
        }
    }
    acc.x += __shfl_xor_sync(0xffffffffu, acc.x, 16);
    acc.y += __shfl_xor_sync(0xffffffffu, acc.y, 16);
    acc.z += __shfl_xor_sync(0xffffffffu, acc.z, 16);
    acc.w += __shfl_xor_sync(0xffffffffu, acc.w, 16);
    if (half == 0) {
        if (FIN == 1) {
            float nw = g_norm[w];
            float vv[4] = {acc.x, acc.y, acc.z, acc.w};
#pragma unroll
            for (int c = 0; c < 4; c++) {
                float x = fmaxf(vv[c] * nw, 0.f);
                uint32_t idx = (uint32_t)w * HID + (uint32_t)(q * 4 + c);
                x = drop_keep(k0, k1, idx) ? 2.f * x : 0.f;
                vv[c] = x * nw;            // pre-scale for layer 2
            }
            acc = make_float4(vv[0], vv[1], vv[2], vv[3]);
        }
        *reinterpret_cast<float4*>(&obuf[(size_t)w * HID + q * 4]) = acc;
    }
}

// ---------------- fin2: 64 nodes / block; h2 + column sums ----------------------
__global__ __launch_bounds__(512) void k_fin2(const float* __restrict__ w2,
                                              uint32_t kb0, uint32_t kb1) {
    __shared__ float sW[64 * 64];
    __shared__ float sIn[64 * 64];
    __shared__ float sPart[8][65];
    int tid = threadIdx.x;
    int nb = blockIdx.x * 64;
#pragma unroll
    for (int l = 0; l < 2; l++) {
        int i = (tid + l * 512) * 4;
        *reinterpret_cast<float4*>(&sW[i]) = *reinterpret_cast<const float4*>(&w2[i]);
    }
#pragma unroll
    for (int l = 0; l < 2; l++) {
        int i = (tid + l * 512) * 4;
        int n = i >> 6;
        float4 v = make_float4(0.f, 0.f, 0.f, 0.f);
        if (nb + n < N_NODES)
            v = *reinterpret_cast<const float4*>(&g_agg2[(size_t)(nb + n) * HID + (i & 63)]);
        *reinterpret_cast<float4*>(&sIn[i]) = v;
    }
    __syncthreads();
    int n  = tid >> 3;
    int cg = tid & 7;
    float acc[8] = {};
    const float* a = &sIn[n * 64];
#pragma unroll
    for (int k = 0; k < 64; k++) {
        float av = a[k];
        float4 b0 = *reinterpret_cast<float4*>(&sW[k * 64 + cg * 8]);
        float4 b1 = *reinterpret_cast<float4*>(&sW[k * 64 + cg * 8 + 4]);
        acc[0] = fmaf(av, b0.x, acc[0]); acc[1] = fmaf(av, b0.y, acc[1]);
        acc[2] = fmaf(av, b0.z, acc[2]); acc[3] = fmaf(av, b0.w, acc[3]);
        acc[4] = fmaf(av, b1.x, acc[4]); acc[5] = fmaf(av, b1.y, acc[5]);
        acc[6] = fmaf(av, b1.z, acc[6]); acc[7] = fmaf(av, b1.w, acc[7]);
    }
    int gn = nb + n;
    float nm = (gn < N_NODES) ? g_norm[gn] : 0.f;
    float vout[8];
#pragma unroll
    for (int c = 0; c < 8; c++) {
        float v = fmaxf(acc[c] * nm, 0.f);
        uint32_t idx = (uint32_t)gn * HID + (uint32_t)(cg * 8 + c);
        v = drop_keep(kb0, kb1, idx) ? 2.f * v : 0.f;
        vout[c] = v;
    }
    if (gn < N_NODES) {
        *reinterpret_cast<float4*>(&g_h2[(size_t)gn * HID + cg * 8]) =
            make_float4(vout[0], vout[1], vout[2], vout[3]);
        *reinterpret_cast<float4*>(&g_h2[(size_t)gn * HID + cg * 8 + 4]) =
            make_float4(vout[4], vout[5], vout[6], vout[7]);
    }
    __syncthreads();
    float* sOut = sW;
#pragma unroll
    for (int c = 0; c < 8; c++)
        sOut[n * 64 + cg * 8 + c] = (gn < N_NODES) ? vout[c] : 0.f;
    __syncthreads();
    {
        int c = tid & 63, chunk = tid >> 6;
        float s = 0.f;
#pragma unroll
        for (int i = 0; i < 8; i++) s += sOut[(chunk * 8 + i) * 64 + c];
        sPart[chunk][c] = s;
    }
    __syncthreads();
    if (tid < 64) {
        float s = 0.f;
#pragma unroll
        for (int i = 0; i < 8; i++) s += sPart[i][tid];
        atomicAdd(&g_colsum[tid], s);
    }
}

// ---------------- conv(mean) + bias ---------------------------------------------
__global__ void k_omean(const float* __restrict__ cw, const float* __restrict__ cb) {
    __shared__ float m[64];
    int t = threadIdx.x;
    if (t < 64) m[t] = g_colsum[t] * (1.f / (float)N_NODES);
    __syncthreads();
    if (t < CONVOUT) {
        int o = t / 62, jj = t % 62;
        g_omean[t] = cw[o * 3 + 0] * m[jj] + cw[o * 3 + 1] * m[jj + 1]
                   + cw[o * 3 + 2] * m[jj + 2] + cb[o];
    }
}

// ---------------- per-node conv + radius + clip ----------------------------------
__global__ void k_final(const float* __restrict__ cw, const float* __restrict__ cb,
                        const float* __restrict__ ref, float* __restrict__ out) {
    __shared__ float sO[CONVOUT];
    int tid = threadIdx.x;
    if (tid < CONVOUT) sO[tid] = g_omean[tid];
    __syncthreads();
    int lane = tid & 31, warp = tid >> 5;
    int node = blockIdx.x * 8 + warp;
    float w00 = cw[0], w01 = cw[1], w02 = cw[2];
    float w10 = cw[3], w11 = cw[4], w12 = cw[5];
    float b0 = cb[0], b1 = cb[1];
    const float* h = &g_h2[(size_t)node * HID];
    float acc = 0.f;
#pragma unroll
    for (int l = 0; l < 4; l++) {
        int j = lane * 4 + l;
        if (j < CONVOUT) {
            float y;
            if (j < 62) y = w00 * h[j] + w01 * h[j + 1] + w02 * h[j + 2] + b0;
            else { int jj = j - 62; y = w10 * h[jj] + w11 * h[jj + 1] + w12 * h[jj + 2] + b1; }
            float d = y - sO[j] + 1e-6f;
            acc += d * d;
        }
    }
#pragma unroll
    for (int o = 16; o; o >>= 1) acc += __shfl_xor_sync(0xffffffffu, acc, o);
    if (lane == 0) {
        float r = sqrtf(acc);
        out[node] = fminf(fmaxf(r - ref[0], 1e-4f), 0.9999f);
    }
    if (blockIdx.x == 0 && tid == 0) out[N_NODES] = ref[0];
}

// ---------------- launch (strictly sequential, single stream) --------------------
extern "C" void kernel_launch(void* const* d_in, const int* in_sizes, int n_in,
                              void* d_out, int out_size) {
    const float* feat = (const float*)d_in[0];
    const float* w1   = (const float*)d_in[1];
    const float* w2   = (const float*)d_in[2];
    const float* cw   = (const float*)d_in[3];
    const float* cb   = (const float*)d_in[4];
    const float* ref  = (const float*)d_in[5];
    const int*   src  = (const int*)d_in[6];
    const int*   dst  = (const int*)d_in[7];
    float* out = (float*)d_out;

    uint32_t ka0 = 0, ka1 = 0, kb0 = 0, kb1 = 1;
    tf2x32(0u, 42u, ka0, ka1);
    tf2x32(0u, 42u, kb0, kb1);

    float* t_ptr;   cudaGetSymbolAddress((void**)&t_ptr, g_t);
    float* h1_ptr;  cudaGetSymbolAddress((void**)&h1_ptr, g_h1);
    float* a2_ptr;  cudaGetSymbolAddress((void**)&a2_ptr, g_agg2);

    k_zero<<<(N_NODES + 255) / 256, 256>>>();
    k_deg<<<(N_EDGES + 255) / 256, 256>>>(dst);
    k_scan1<<<NSCANB, SCAN_B>>>();
    k_scan2<<<1, 128>>>();
    k_scan3<<<(N_NODES + 255) / 256, 256>>>();
    k_fill<<<(N_EDGES + 255) / 256, 256>>>(src, dst);
    k_gemm1<<<(N_NODES + 127) / 128, 256>>>(feat, w1);
    k_gather<1><<<(N_NODES * 32 + 255) / 256, 256>>>(t_ptr, h1_ptr, ka0, ka1);
    k_gather<0><<<(N_NODES * 32 + 255) / 256, 256>>>(h1_ptr, a2_ptr, 0u, 0u);
    k_fin2<<<(N_NODES + 63) / 64, 512>>>(w2, kb0, kb1);
    k_omean<<<1, 128>>>(cw, cb);
    k_final<<<N_NODES / 8, 256>>>(cw, cb, ref, out);
}

// round 6
// speedup vs baseline: 1.1089x; 1.1089x over previous
#include <cuda_runtime.h>
#include <cstdint>

#define N_NODES 100000
#define N_EDGES 1600000
#define IN_DIM  128
#define HID     64
#define CONVOUT 124   // 2 * 62
#define SCAN_B  1024
#define NSCANB  ((N_NODES + SCAN_B - 1) / SCAN_B)   // 98

// ---------------- scratch (static device globals; no allocs allowed) ----------
__device__ float g_t   [N_NODES * HID];   // (feat@w1)*norm
__device__ float g_h1  [N_NODES * HID];   // dropout(relu(agg*norm))*norm
__device__ float g_agg2[N_NODES * HID];   // layer-2 aggregate
__device__ float g_h2  [N_NODES * HID];   // final node features
__device__ int   g_deg [N_NODES];
__device__ int   g_cnt [N_NODES];
__device__ float g_norm[N_NODES];
__device__ int   g_rowptr[N_NODES + 1];
__device__ int   g_bsum[NSCANB];
__device__ int   g_boff[NSCANB];
__device__ int   g_csr[N_EDGES];          // src ids grouped by dst
__device__ float g_colsum[HID];
__device__ float g_omean[CONVOUT];

// ---------------- threefry2x32 (20 rounds, JAX-compatible) --------------------
__host__ __device__ __forceinline__ void tf2x32(uint32_t k0, uint32_t k1,
                                                uint32_t& x0, uint32_t& x1) {
    uint32_t ks2 = k0 ^ k1 ^ 0x1BD11BDAu;
#define TF_R(r) { x0 += x1; x1 = (x1 << (r)) | (x1 >> (32 - (r))); x1 ^= x0; }
    x0 += k0; x1 += k1;
    TF_R(13) TF_R(15) TF_R(26) TF_R(6)   x0 += k1;  x1 += ks2 + 1u;
    TF_R(17) TF_R(29) TF_R(16) TF_R(24)  x0 += ks2; x1 += k0  + 2u;
    TF_R(13) TF_R(15) TF_R(26) TF_R(6)   x0 += k0;  x1 += k1  + 3u;
    TF_R(17) TF_R(29) TF_R(16) TF_R(24)  x0 += k1;  x1 += ks2 + 4u;
    TF_R(13) TF_R(15) TF_R(26) TF_R(6)   x0 += ks2; x1 += k0  + 5u;
#undef TF_R
}

__device__ __forceinline__ bool drop_keep(uint32_t k0, uint32_t k1, uint32_t idx) {
    uint32_t x0 = 0u, x1 = idx;
    tf2x32(k0, k1, x0, x1);
    return ((x0 ^ x1) & 0x80000000u) == 0u;
}

// ---------------- graph prep ---------------------------------------------------
__global__ void k_zero() {
    int i = blockIdx.x * blockDim.x + threadIdx.x;
    if (i < N_NODES) { g_deg[i] = 0; g_cnt[i] = 0; }
    if (i < HID) g_colsum[i] = 0.f;
}

__global__ void k_deg(const int* __restrict__ dst) {
    int e = blockIdx.x * blockDim.x + threadIdx.x;
    if (e < N_EDGES) atomicAdd(&g_deg[dst[e]], 1);
}

__global__ void k_scan1() {
    __shared__ int s[SCAN_B];
    int t = threadIdx.x, b = blockIdx.x;
    int i = b * SCAN_B + t;
    int v = (i < N_NODES) ? g_deg[i] : 0;
    s[t] = v;
    __syncthreads();
#pragma unroll
    for (int off = 1; off < SCAN_B; off <<= 1) {
        int add = (t >= off) ? s[t - off] : 0;
        __syncthreads();
        s[t] += add;
        __syncthreads();
    }
    if (i < N_NODES) g_rowptr[i + 1] = s[t];
    if (t == SCAN_B - 1) g_bsum[b] = s[t];
}

__global__ void k_scan2() {
    __shared__ int s[128];
    int t = threadIdx.x;
    int v = (t < NSCANB) ? g_bsum[t] : 0;
    s[t] = v;
    __syncthreads();
#pragma unroll
    for (int off = 1; off < 128; off <<= 1) {
        int add = (t >= off) ? s[t - off] : 0;
        __syncthreads();
        s[t] += add;
        __syncthreads();
    }
    if (t < NSCANB) g_boff[t] = s[t] - v;   // exclusive
}

__global__ void k_scan3() {
    int i = blockIdx.x * blockDim.x + threadIdx.x;
    if (i < N_NODES) {
        g_rowptr[i + 1] += g_boff[i >> 10];
        g_norm[i] = rsqrtf((float)(g_deg[i] + 1));
    }
    if (i == 0) g_rowptr[0] = 0;
}

__global__ void k_fill(const int* __restrict__ src, const int* __restrict__ dst) {
    int e = blockIdx.x * blockDim.x + threadIdx.x;
    if (e >= N_EDGES) return;
    int d = dst[e];
    int ofs = atomicAdd(&g_cnt[d], 1);
    g_csr[g_rowptr[d] + ofs] = src[e];
}

// ---------------- gemm1: g_t = (feat @ w1) * norm -------------------------------
__global__ __launch_bounds__(256) void k_gemm1(const float* __restrict__ feat,
                                               const float* __restrict__ w1) {
    __shared__ float sA[16][132];
    __shared__ float sB[16][64];
    int tid = threadIdx.x;
    int nb  = blockIdx.x * 128;
    int tx  = tid & 15;
    int ty  = tid >> 4;
    float acc[8][4] = {};
#pragma unroll
    for (int kc = 0; kc < 8; kc++) {
#pragma unroll
        for (int l = 0; l < 2; l++) {
            int idx = tid + l * 256;
            int nd  = idx >> 2;
            int kq  = idx & 3;
            int gn  = nb + nd;
            float4 v = make_float4(0.f, 0.f, 0.f, 0.f);
            if (gn < N_NODES)
                v = *reinterpret_cast<const float4*>(&feat[(size_t)gn * IN_DIM + kc * 16 + kq * 4]);
            sA[kq * 4 + 0][nd] = v.x;
            sA[kq * 4 + 1][nd] = v.y;
            sA[kq * 4 + 2][nd] = v.z;
            sA[kq * 4 + 3][nd] = v.w;
        }
        {
            int kk = tid >> 4, c4 = tid & 15;
            float4 v = *reinterpret_cast<const float4*>(&w1[(kc * 16 + kk) * HID + c4 * 4]);
            *reinterpret_cast<float4*>(&sB[kk][c4 * 4]) = v;
        }
        __syncthreads();
#pragma unroll
        for (int kk = 0; kk < 16; kk++) {
            float4 b  = *reinterpret_cast<float4*>(&sB[kk][tx * 4]);
            float4 a0 = *reinterpret_cast<float4*>(&sA[kk][ty * 8]);
            float4 a1 = *reinterpret_cast<float4*>(&sA[kk][ty * 8 + 4]);
            float av[8] = {a0.x, a0.y, a0.z, a0.w, a1.x, a1.y, a1.z, a1.w};
#pragma unroll
            for (int i = 0; i < 8; i++) {
                acc[i][0] = fmaf(av[i], b.x, acc[i][0]);
                acc[i][1] = fmaf(av[i], b.y, acc[i][1]);
                acc[i][2] = fmaf(av[i], b.z, acc[i][2]);
                acc[i][3] = fmaf(av[i], b.w, acc[i][3]);
            }
        }
        __syncthreads();
    }
#pragma unroll
    for (int i = 0; i < 8; i++) {
        int gn = nb + ty * 8 + i;
        if (gn < N_NODES) {
            float nm = g_norm[gn];
            float4 v = make_float4(acc[i][0] * nm, acc[i][1] * nm,
                                   acc[i][2] * nm, acc[i][3] * nm);
            *reinterpret_cast<float4*>(&g_t[(size_t)gn * HID + tx * 4]) = v;
        }
    }
}

// ---------------- gather: warp per dst node, float2/lane (R2 shape) -------------
// FIN=1: fused fin1 epilogue (norm, relu, dropout, *norm). FIN=0: raw sum store.
template<int FIN>
__global__ __launch_bounds__(256) void k_gather(const float* __restrict__ sbuf,
                                                float* __restrict__ obuf,
                                                uint32_t k0, uint32_t k1) {
    int w = (blockIdx.x * blockDim.x + threadIdx.x) >> 5;
    if (w >= N_NODES) return;
    int lane = threadIdx.x & 31;
    int beg = g_rowptr[w], end = g_rowptr[w + 1];
    const float* sbl = sbuf + lane * 2;          // lane-fixed base
    float2 acc = *reinterpret_cast<const float2*>(&sbl[(size_t)w * HID]);  // self loop
    for (int base = beg; base < end; base += 32) {
        int j = base + lane;
        int off = (j < end) ? g_csr[j] * HID : 0;   // premultiplied row offset
        int cnt = min(32, end - base);
#pragma unroll 8
        for (int t = 0; t < cnt; t++) {
            int so = __shfl_sync(0xffffffffu, off, t);
            float2 v = *reinterpret_cast<const float2*>(&sbl[so]);
            acc.x += v.x; acc.y += v.y;
        }
    }
    if (FIN == 1) {
        float nw = g_norm[w];
        acc.x = fmaxf(acc.x * nw, 0.f);
        acc.y = fmaxf(acc.y * nw, 0.f);
        uint32_t idx = (uint32_t)w * HID + (uint32_t)(lane * 2);
        acc.x = drop_keep(k0, k1, idx)     ? 2.f * acc.x : 0.f;
        acc.y = drop_keep(k0, k1, idx + 1) ? 2.f * acc.y : 0.f;
        acc.x *= nw; acc.y *= nw;                // pre-scale for layer 2
    }
    *reinterpret_cast<float2*>(&obuf[(size_t)w * HID + lane * 2]) = acc;
}

// ---------------- fin2: 64 nodes / block; h2 + column sums ----------------------
__global__ __launch_bounds__(512) void k_fin2(const float* __restrict__ w2,
                                              uint32_t kb0, uint32_t kb1) {
    __shared__ float sW[64 * 64];
    __shared__ float sIn[64 * 64];
    __shared__ float sPart[8][65];
    int tid = threadIdx.x;
    int nb = blockIdx.x * 64;
#pragma unroll
    for (int l = 0; l < 2; l++) {
        int i = (tid + l * 512) * 4;
        *reinterpret_cast<float4*>(&sW[i]) = *reinterpret_cast<const float4*>(&w2[i]);
    }
#pragma unroll
    for (int l = 0; l < 2; l++) {
        int i = (tid + l * 512) * 4;
        int n = i >> 6;
        float4 v = make_float4(0.f, 0.f, 0.f, 0.f);
        if (nb + n < N_NODES)
            v = *reinterpret_cast<const float4*>(&g_agg2[(size_t)(nb + n) * HID + (i & 63)]);
        *reinterpret_cast<float4*>(&sIn[i]) = v;
    }
    __syncthreads();
    int n  = tid >> 3;
    int cg = tid & 7;
    float acc[8] = {};
    const float* a = &sIn[n * 64];
#pragma unroll
    for (int k = 0; k < 64; k++) {
        float av = a[k];
        float4 b0 = *reinterpret_cast<float4*>(&sW[k * 64 + cg * 8]);
        float4 b1 = *reinterpret_cast<float4*>(&sW[k * 64 + cg * 8 + 4]);
        acc[0] = fmaf(av, b0.x, acc[0]); acc[1] = fmaf(av, b0.y, acc[1]);
        acc[2] = fmaf(av, b0.z, acc[2]); acc[3] = fmaf(av, b0.w, acc[3]);
        acc[4] = fmaf(av, b1.x, acc[4]); acc[5] = fmaf(av, b1.y, acc[5]);
        acc[6] = fmaf(av, b1.z, acc[6]); acc[7] = fmaf(av, b1.w, acc[7]);
    }
    int gn = nb + n;
    float nm = (gn < N_NODES) ? g_norm[gn] : 0.f;
    float vout[8];
#pragma unroll
    for (int c = 0; c < 8; c++) {
        float v = fmaxf(acc[c] * nm, 0.f);
        uint32_t idx = (uint32_t)gn * HID + (uint32_t)(cg * 8 + c);
        v = drop_keep(kb0, kb1, idx) ? 2.f * v : 0.f;
        vout[c] = v;
    }
    if (gn < N_NODES) {
        *reinterpret_cast<float4*>(&g_h2[(size_t)gn * HID + cg * 8]) =
            make_float4(vout[0], vout[1], vout[2], vout[3]);
        *reinterpret_cast<float4*>(&g_h2[(size_t)gn * HID + cg * 8 + 4]) =
            make_float4(vout[4], vout[5], vout[6], vout[7]);
    }
    __syncthreads();
    float* sOut = sW;
#pragma unroll
    for (int c = 0; c < 8; c++)
        sOut[n * 64 + cg * 8 + c] = (gn < N_NODES) ? vout[c] : 0.f;
    __syncthreads();
    {
        int c = tid & 63, chunk = tid >> 6;
        float s = 0.f;
#pragma unroll
        for (int i = 0; i < 8; i++) s += sOut[(chunk * 8 + i) * 64 + c];
        sPart[chunk][c] = s;
    }
    __syncthreads();
    if (tid < 64) {
        float s = 0.f;
#pragma unroll
        for (int i = 0; i < 8; i++) s += sPart[i][tid];
        atomicAdd(&g_colsum[tid], s);
    }
}

// ---------------- conv(mean) + bias ---------------------------------------------
__global__ void k_omean(const float* __restrict__ cw, const float* __restrict__ cb) {
    __shared__ float m[64];
    int t = threadIdx.x;
    if (t < 64) m[t] = g_colsum[t] * (1.f / (float)N_NODES);
    __syncthreads();
    if (t < CONVOUT) {
        int o = t / 62, jj = t % 62;
        g_omean[t] = cw[o * 3 + 0] * m[jj] + cw[o * 3 + 1] * m[jj + 1]
                   + cw[o * 3 + 2] * m[jj + 2] + cb[o];
    }
}

// ---------------- per-node conv + radius + clip ----------------------------------
__global__ void k_final(const float* __restrict__ cw, const float* __restrict__ cb,
                        const float* __restrict__ ref, float* __restrict__ out) {
    __shared__ float sO[CONVOUT];
    int tid = threadIdx.x;
    if (tid < CONVOUT) sO[tid] = g_omean[tid];
    __syncthreads();
    int lane = tid & 31, warp = tid >> 5;
    int node = blockIdx.x * 8 + warp;
    float w00 = cw[0], w01 = cw[1], w02 = cw[2];
    float w10 = cw[3], w11 = cw[4], w12 = cw[5];
    float b0 = cb[0], b1 = cb[1];
    const float* h = &g_h2[(size_t)node * HID];
    float acc = 0.f;
#pragma unroll
    for (int l = 0; l < 4; l++) {
        int j = lane * 4 + l;
        if (j < CONVOUT) {
            float y;
            if (j < 62) y = w00 * h[j] + w01 * h[j + 1] + w02 * h[j + 2] + b0;
            else { int jj = j - 62; y = w10 * h[jj] + w11 * h[jj + 1] + w12 * h[jj + 2] + b1; }
            float d = y - sO[j] + 1e-6f;
            acc += d * d;
        }
    }
#pragma unroll
    for (int o = 16; o; o >>= 1) acc += __shfl_xor_sync(0xffffffffu, acc, o);
    if (lane == 0) {
        float r = sqrtf(acc);
        out[node] = fminf(fmaxf(r - ref[0], 1e-4f), 0.9999f);
    }
    if (blockIdx.x == 0 && tid == 0) out[N_NODES] = ref[0];
}

// ---------------- launch (strictly sequential, single stream) --------------------
extern "C" void kernel_launch(void* const* d_in, const int* in_sizes, int n_in,
                              void* d_out, int out_size) {
    const float* feat = (const float*)d_in[0];
    const float* w1   = (const float*)d_in[1];
    const float* w2   = (const float*)d_in[2];
    const float* cw   = (const float*)d_in[3];
    const float* cb   = (const float*)d_in[4];
    const float* ref  = (const float*)d_in[5];
    const int*   src  = (const int*)d_in[6];
    const int*   dst  = (const int*)d_in[7];
    float* out = (float*)d_out;

    uint32_t ka0 = 0, ka1 = 0, kb0 = 0, kb1 = 1;
    tf2x32(0u, 42u, ka0, ka1);
    tf2x32(0u, 42u, kb0, kb1);

    float* t_ptr;   cudaGetSymbolAddress((void**)&t_ptr, g_t);
    float* h1_ptr;  cudaGetSymbolAddress((void**)&h1_ptr, g_h1);
    float* a2_ptr;  cudaGetSymbolAddress((void**)&a2_ptr, g_agg2);

    k_zero<<<(N_NODES + 255) / 256, 256>>>();
    k_deg<<<(N_EDGES + 255) / 256, 256>>>(dst);
    k_scan1<<<NSCANB, SCAN_B>>>();
    k_scan2<<<1, 128>>>();
    k_scan3<<<(N_NODES + 255) / 256, 256>>>();
    k_fill<<<(N_EDGES + 255) / 256, 256>>>(src, dst);
    k_gemm1<<<(N_NODES + 127) / 128, 256>>>(feat, w1);
    k_gather<1><<<(N_NODES * 32 + 255) / 256, 256>>>(t_ptr, h1_ptr, ka0, ka1);
    k_gather<0><<<(N_NODES * 32 + 255) / 256, 256>>>(h1_ptr, a2_ptr, 0u, 0u);
    k_fin2<<<(N_NODES + 63) / 64, 512>>>(w2, kb0, kb1);
    k_omean<<<1, 128>>>(cw, cb);
    k_final<<<N_NODES / 8, 256>>>(cw, cb, ref, out);
}

// round 7
// speedup vs baseline: 1.1179x; 1.0082x over previous
#include <cuda_runtime.h>
#include <cstdint>

#define N_NODES 100000
#define N_EDGES 1600000
#define IN_DIM  128
#define HID     64
#define CONVOUT 124   // 2 * 62
#define SCAN_B  1024
#define NSCANB  ((N_NODES + SCAN_B - 1) / SCAN_B)   // 98

typedef unsigned long long ull;

// ---------------- packed f32x2 helpers (Blackwell FFMA2) -----------------------
__device__ __forceinline__ ull pack2(float x, float y) {
    ull r;
    asm("mov.b64 %0, {%1, %2};" : "=l"(r) : "f"(x), "f"(y));
    return r;
}
__device__ __forceinline__ void unpack2(ull v, float& x, float& y) {
    asm("mov.b64 {%0, %1}, %2;" : "=f"(x), "=f"(y) : "l"(v));
}
__device__ __forceinline__ void fma2(ull& d, ull a, ull b) {
    asm("fma.rn.f32x2 %0, %1, %2, %0;" : "+l"(d) : "l"(a), "l"(b));
}

// ---------------- scratch (static device globals; no allocs allowed) ----------
__device__ float g_t   [N_NODES * HID];   // (feat@w1)*norm
__device__ float g_h1  [N_NODES * HID];   // dropout(relu(agg*norm))*norm
__device__ float g_agg2[N_NODES * HID];   // layer-2 aggregate
__device__ float g_h2  [N_NODES * HID];   // final node features
__device__ int   g_deg [N_NODES];
__device__ int   g_cnt [N_NODES];
__device__ float g_norm[N_NODES];
__device__ int   g_rowptr[N_NODES + 1];
__device__ int   g_bsum[NSCANB];
__device__ int   g_boff[NSCANB];
__device__ int   g_csr[N_EDGES];          // src ids grouped by dst
__device__ float g_colsum[HID];
__device__ float g_omean[CONVOUT];

// ---------------- threefry2x32 (20 rounds, JAX-compatible) --------------------
__host__ __device__ __forceinline__ void tf2x32(uint32_t k0, uint32_t k1,
                                                uint32_t& x0, uint32_t& x1) {
    uint32_t ks2 = k0 ^ k1 ^ 0x1BD11BDAu;
#define TF_R(r) { x0 += x1; x1 = (x1 << (r)) | (x1 >> (32 - (r))); x1 ^= x0; }
    x0 += k0; x1 += k1;
    TF_R(13) TF_R(15) TF_R(26) TF_R(6)   x0 += k1;  x1 += ks2 + 1u;
    TF_R(17) TF_R(29) TF_R(16) TF_R(24)  x0 += ks2; x1 += k0  + 2u;
    TF_R(13) TF_R(15) TF_R(26) TF_R(6)   x0 += k0;  x1 += k1  + 3u;
    TF_R(17) TF_R(29) TF_R(16) TF_R(24)  x0 += k1;  x1 += ks2 + 4u;
    TF_R(13) TF_R(15) TF_R(26) TF_R(6)   x0 += ks2; x1 += k0  + 5u;
#undef TF_R
}

__device__ __forceinline__ bool drop_keep(uint32_t k0, uint32_t k1, uint32_t idx) {
    uint32_t x0 = 0u, x1 = idx;
    tf2x32(k0, k1, x0, x1);
    return ((x0 ^ x1) & 0x80000000u) == 0u;
}

// ---------------- graph prep ---------------------------------------------------
__global__ void k_zero() {
    int i = blockIdx.x * blockDim.x + threadIdx.x;
    if (i < N_NODES) { g_deg[i] = 0; g_cnt[i] = 0; }
    if (i < HID) g_colsum[i] = 0.f;
}

__global__ void k_deg(const int* __restrict__ dst) {
    int e = blockIdx.x * blockDim.x + threadIdx.x;
    if (e < N_EDGES) atomicAdd(&g_deg[dst[e]], 1);
}

__global__ void k_scan1() {
    __shared__ int s[SCAN_B];
    int t = threadIdx.x, b = blockIdx.x;
    int i = b * SCAN_B + t;
    int v = (i < N_NODES) ? g_deg[i] : 0;
    s[t] = v;
    __syncthreads();
#pragma unroll
    for (int off = 1; off < SCAN_B; off <<= 1) {
        int add = (t >= off) ? s[t - off] : 0;
        __syncthreads();
        s[t] += add;
        __syncthreads();
    }
    if (i < N_NODES) g_rowptr[i + 1] = s[t];
    if (t == SCAN_B - 1) g_bsum[b] = s[t];
}

__global__ void k_scan2() {
    __shared__ int s[128];
    int t = threadIdx.x;
    int v = (t < NSCANB) ? g_bsum[t] : 0;
    s[t] = v;
    __syncthreads();
#pragma unroll
    for (int off = 1; off < 128; off <<= 1) {
        int add = (t >= off) ? s[t - off] : 0;
        __syncthreads();
        s[t] += add;
        __syncthreads();
    }
    if (t < NSCANB) g_boff[t] = s[t] - v;   // exclusive
}

__global__ void k_scan3() {
    int i = blockIdx.x * blockDim.x + threadIdx.x;
    if (i < N_NODES) {
        g_rowptr[i + 1] += g_boff[i >> 10];
        g_norm[i] = rsqrtf((float)(g_deg[i] + 1));
    }
    if (i == 0) g_rowptr[0] = 0;
}

__global__ void k_fill(const int* __restrict__ src, const int* __restrict__ dst) {
    int e = blockIdx.x * blockDim.x + threadIdx.x;
    if (e >= N_EDGES) return;
    int d = dst[e];
    int ofs = atomicAdd(&g_cnt[d], 1);
    g_csr[g_rowptr[d] + ofs] = src[e];
}

// ---------------- gemm1: g_t = (feat @ w1) * norm  (FFMA2 inner loop) -----------
__global__ __launch_bounds__(256) void k_gemm1(const float* __restrict__ feat,
                                               const float* __restrict__ w1) {
    __shared__ float sA[16][132];   // k-major; row = 528B (8B-aligned)
    __shared__ float sB[16][64];
    int tid = threadIdx.x;
    int nb  = blockIdx.x * 128;
    int tx  = tid & 15;             // col group (4 cols)
    int ty  = tid >> 4;             // node group (8 nodes)
    // acc2[p][c]: node pair p (nodes ty*8+2p, +2p+1), column tx*4+c
    ull acc2[4][4];
#pragma unroll
    for (int p = 0; p < 4; p++)
#pragma unroll
        for (int c = 0; c < 4; c++) acc2[p][c] = 0ull;

#pragma unroll
    for (int kc = 0; kc < 8; kc++) {
#pragma unroll
        for (int l = 0; l < 2; l++) {
            int idx = tid + l * 256;
            int nd  = idx >> 2;
            int kq  = idx & 3;
            int gn  = nb + nd;
            float4 v = make_float4(0.f, 0.f, 0.f, 0.f);
            if (gn < N_NODES)
                v = *reinterpret_cast<const float4*>(&feat[(size_t)gn * IN_DIM + kc * 16 + kq * 4]);
            sA[kq * 4 + 0][nd] = v.x;
            sA[kq * 4 + 1][nd] = v.y;
            sA[kq * 4 + 2][nd] = v.z;
            sA[kq * 4 + 3][nd] = v.w;
        }
        {
            int kk = tid >> 4, c4 = tid & 15;
            float4 v = *reinterpret_cast<const float4*>(&w1[(kc * 16 + kk) * HID + c4 * 4]);
            *reinterpret_cast<float4*>(&sB[kk][c4 * 4]) = v;
        }
        __syncthreads();
#pragma unroll
        for (int kk = 0; kk < 16; kk++) {
            float4 b = *reinterpret_cast<float4*>(&sB[kk][tx * 4]);
            ull bb[4];
            bb[0] = pack2(b.x, b.x); bb[1] = pack2(b.y, b.y);
            bb[2] = pack2(b.z, b.z); bb[3] = pack2(b.w, b.w);
#pragma unroll
            for (int p = 0; p < 4; p++) {
                ull a2 = *reinterpret_cast<ull*>(&sA[kk][ty * 8 + 2 * p]); // 2 adjacent nodes
                fma2(acc2[p][0], a2, bb[0]);
                fma2(acc2[p][1], a2, bb[1]);
                fma2(acc2[p][2], a2, bb[2]);
                fma2(acc2[p][3], a2, bb[3]);
            }
        }
        __syncthreads();
    }
#pragma unroll
    for (int p = 0; p < 4; p++) {
        float lo[4], hi[4];
#pragma unroll
        for (int c = 0; c < 4; c++) unpack2(acc2[p][c], lo[c], hi[c]);
        int gn0 = nb + ty * 8 + 2 * p;
        int gn1 = gn0 + 1;
        if (gn0 < N_NODES) {
            float nm = g_norm[gn0];
            float4 v = make_float4(lo[0] * nm, lo[1] * nm, lo[2] * nm, lo[3] * nm);
            *reinterpret_cast<float4*>(&g_t[(size_t)gn0 * HID + tx * 4]) = v;
        }
        if (gn1 < N_NODES) {
            float nm = g_norm[gn1];
            float4 v = make_float4(hi[0] * nm, hi[1] * nm, hi[2] * nm, hi[3] * nm);
            *reinterpret_cast<float4*>(&g_t[(size_t)gn1 * HID + tx * 4]) = v;
        }
    }
}

// ---------------- gather: warp per dst node, float2/lane ------------------------
// FIN=1: fused fin1 epilogue (norm, relu, dropout, *norm). FIN=0: raw sum store.
template<int FIN>
__global__ __launch_bounds__(256) void k_gather(const float* __restrict__ sbuf,
                                                float* __restrict__ obuf,
                                                uint32_t k0, uint32_t k1) {
    int w = (blockIdx.x * blockDim.x + threadIdx.x) >> 5;
    if (w >= N_NODES) return;
    int lane = threadIdx.x & 31;
    int beg = g_rowptr[w], end = g_rowptr[w + 1];
    const float* sbl = sbuf + lane * 2;          // lane-fixed base
    float2 acc = *reinterpret_cast<const float2*>(&sbl[(size_t)w * HID]);  // self loop
    for (int base = beg; base < end; base += 32) {
        int j = base + lane;
        int off = (j < end) ? g_csr[j] * HID : 0;   // premultiplied row offset
        int cnt = min(32, end - base);
#pragma unroll 8
        for (int t = 0; t < cnt; t++) {
            int so = __shfl_sync(0xffffffffu, off, t);
            float2 v = *reinterpret_cast<const float2*>(&sbl[so]);
            acc.x += v.x; acc.y += v.y;
        }
    }
    if (FIN == 1) {
        float nw = g_norm[w];
        acc.x = fmaxf(acc.x * nw, 0.f);
        acc.y = fmaxf(acc.y * nw, 0.f);
        uint32_t idx = (uint32_t)w * HID + (uint32_t)(lane * 2);
        acc.x = drop_keep(k0, k1, idx)     ? 2.f * acc.x : 0.f;
        acc.y = drop_keep(k0, k1, idx + 1) ? 2.f * acc.y : 0.f;
        acc.x *= nw; acc.y *= nw;                // pre-scale for layer 2
    }
    *reinterpret_cast<float2*>(&obuf[(size_t)w * HID + lane * 2]) = acc;
}

// ---------------- fin2: 64 nodes / block; FFMA2 inner loop ----------------------
__global__ __launch_bounds__(512) void k_fin2(const float* __restrict__ w2,
                                              uint32_t kb0, uint32_t kb1) {
    __shared__ float sW[64 * 64];
    __shared__ float sIn[64 * 64];
    __shared__ float sPart[8][65];
    int tid = threadIdx.x;
    int nb = blockIdx.x * 64;
#pragma unroll
    for (int l = 0; l < 2; l++) {
        int i = (tid + l * 512) * 4;
        *reinterpret_cast<float4*>(&sW[i]) = *reinterpret_cast<const float4*>(&w2[i]);
    }
#pragma unroll
    for (int l = 0; l < 2; l++) {
        int i = (tid + l * 512) * 4;
        int n = i >> 6;
        float4 v = make_float4(0.f, 0.f, 0.f, 0.f);
        if (nb + n < N_NODES)
            v = *reinterpret_cast<const float4*>(&g_agg2[(size_t)(nb + n) * HID + (i & 63)]);
        *reinterpret_cast<float4*>(&sIn[i]) = v;
    }
    __syncthreads();
    int n  = tid >> 3;           // local node 0..63
    int cg = tid & 7;            // col group, 8 cols (4 f32x2 pairs)
    ull acc2[4] = {0ull, 0ull, 0ull, 0ull};
    const float* a = &sIn[n * 64];
#pragma unroll
    for (int k = 0; k < 64; k++) {
        ull av2 = pack2(a[k], a[k]);
        const ull* bp = reinterpret_cast<const ull*>(&sW[k * 64 + cg * 8]);
        fma2(acc2[0], av2, bp[0]);
        fma2(acc2[1], av2, bp[1]);
        fma2(acc2[2], av2, bp[2]);
        fma2(acc2[3], av2, bp[3]);
    }
    float accf[8];
#pragma unroll
    for (int j = 0; j < 4; j++) unpack2(acc2[j], accf[2 * j], accf[2 * j + 1]);
    int gn = nb + n;
    float nm = (gn < N_NODES) ? g_norm[gn] : 0.f;
    float vout[8];
#pragma unroll
    for (int c = 0; c < 8; c++) {
        float v = fmaxf(accf[c] * nm, 0.f);
        uint32_t idx = (uint32_t)gn * HID + (uint32_t)(cg * 8 + c);
        v = drop_keep(kb0, kb1, idx) ? 2.f * v : 0.f;
        vout[c] = v;
    }
    if (gn < N_NODES) {
        *reinterpret_cast<float4*>(&g_h2[(size_t)gn * HID + cg * 8]) =
            make_float4(vout[0], vout[1], vout[2], vout[3]);
        *reinterpret_cast<float4*>(&g_h2[(size_t)gn * HID + cg * 8 + 4]) =
            make_float4(vout[4], vout[5], vout[6], vout[7]);
    }
    __syncthreads();
    float* sOut = sW;
#pragma unroll
    for (int c = 0; c < 8; c++)
        sOut[n * 64 + cg * 8 + c] = (gn < N_NODES) ? vout[c] : 0.f;
    __syncthreads();
    {
        int c = tid & 63, chunk = tid >> 6;
        float s = 0.f;
#pragma unroll
        for (int i = 0; i < 8; i++) s += sOut[(chunk * 8 + i) * 64 + c];
        sPart[chunk][c] = s;
    }
    __syncthreads();
    if (tid < 64) {
        float s = 0.f;
#pragma unroll
        for (int i = 0; i < 8; i++) s += sPart[i][tid];
        atomicAdd(&g_colsum[tid], s);
    }
}

// ---------------- conv(mean) + bias ---------------------------------------------
__global__ void k_omean(const float* __restrict__ cw, const float* __restrict__ cb) {
    __shared__ float m[64];
    int t = threadIdx.x;
    if (t < 64) m[t] = g_colsum[t] * (1.f / (float)N_NODES);
    __syncthreads();
    if (t < CONVOUT) {
        int o = t / 62, jj = t % 62;
        g_omean[t] = cw[o * 3 + 0] * m[jj] + cw[o * 3 + 1] * m[jj + 1]
                   + cw[o * 3 + 2] * m[jj + 2] + cb[o];
    }
}

// ---------------- per-node conv + radius + clip ----------------------------------
__global__ void k_final(const float* __restrict__ cw, const float* __restrict__ cb,
                        const float* __restrict__ ref, float* __restrict__ out) {
    __shared__ float sO[CONVOUT];
    int tid = threadIdx.x;
    if (tid < CONVOUT) sO[tid] = g_omean[tid];
    __syncthreads();
    int lane = tid & 31, warp = tid >> 5;
    int node = blockIdx.x * 8 + warp;
    float w00 = cw[0], w01 = cw[1], w02 = cw[2];
    float w10 = cw[3], w11 = cw[4], w12 = cw[5];
    float b0 = cb[0], b1 = cb[1];
    const float* h = &g_h2[(size_t)node * HID];
    float acc = 0.f;
#pragma unroll
    for (int l = 0; l < 4; l++) {
        int j = lane * 4 + l;
        if (j < CONVOUT) {
            float y;
            if (j < 62) y = w00 * h[j] + w01 * h[j + 1] + w02 * h[j + 2] + b0;
            else { int jj = j - 62; y = w10 * h[jj] + w11 * h[jj + 1] + w12 * h[jj + 2] + b1; }
            float d = y - sO[j] + 1e-6f;
            acc += d * d;
        }
    }
#pragma unroll
    for (int o = 16; o; o >>= 1) acc += __shfl_xor_sync(0xffffffffu, acc, o);
    if (lane == 0) {
        float r = sqrtf(acc);
        out[node] = fminf(fmaxf(r - ref[0], 1e-4f), 0.9999f);
    }
    if (blockIdx.x == 0 && tid == 0) out[N_NODES] = ref[0];
}

// ---------------- launch (strictly sequential, single stream) --------------------
extern "C" void kernel_launch(void* const* d_in, const int* in_sizes, int n_in,
                              void* d_out, int out_size) {
    const float* feat = (const float*)d_in[0];
    const float* w1   = (const float*)d_in[1];
    const float* w2   = (const float*)d_in[2];
    const float* cw   = (const float*)d_in[3];
    const float* cb   = (const float*)d_in[4];
    const float* ref  = (const float*)d_in[5];
    const int*   src  = (const int*)d_in[6];
    const int*   dst  = (const int*)d_in[7];
    float* out = (float*)d_out;

    uint32_t ka0 = 0, ka1 = 0, kb0 = 0, kb1 = 1;
    tf2x32(0u, 42u, ka0, ka1);
    tf2x32(0u, 42u, kb0, kb1);

    float* t_ptr;   cudaGetSymbolAddress((void**)&t_ptr, g_t);
    float* h1_ptr;  cudaGetSymbolAddress((void**)&h1_ptr, g_h1);
    float* a2_ptr;  cudaGetSymbolAddress((void**)&a2_ptr, g_agg2);

    k_zero<<<(N_NODES + 255) / 256, 256>>>();
    k_deg<<<(N_EDGES + 255) / 256, 256>>>(dst);
    k_scan1<<<NSCANB, SCAN_B>>>();
    k_scan2<<<1, 128>>>();
    k_scan3<<<(N_NODES + 255) / 256, 256>>>();
    k_fill<<<(N_EDGES + 255) / 256, 256>>>(src, dst);
    k_gemm1<<<(N_NODES + 127) / 128, 256>>>(feat, w1);
    k_gather<1><<<(N_NODES * 32 + 255) / 256, 256>>>(t_ptr, h1_ptr, ka0, ka1);
    k_gather<0><<<(N_NODES * 32 + 255) / 256, 256>>>(h1_ptr, a2_ptr, 0u, 0u);
    k_fin2<<<(N_NODES + 63) / 64, 512>>>(w2, kb0, kb1);
    k_omean<<<1, 128>>>(cw, cb);
    k_final<<<N_NODES / 8, 256>>>(cw, cb, ref, out);
}

// round 9
// speedup vs baseline: 1.1205x; 1.0023x over previous
#include <cuda_runtime.h>
#include <cstdint>

#define N_NODES 100000
#define N_EDGES 1600000
#define IN_DIM  128
#define HID     64
#define CONVOUT 124   // 2 * 62
#define SCAN_B  1024
#define NSCANB  ((N_NODES + SCAN_B - 1) / SCAN_B)   // 98

typedef unsigned long long ull;

// ---------------- packed f32x2 helpers (Blackwell FFMA2) -----------------------
__device__ __forceinline__ ull pack2(float x, float y) {
    ull r;
    asm("mov.b64 %0, {%1, %2};" : "=l"(r) : "f"(x), "f"(y));
    return r;
}
__device__ __forceinline__ void unpack2(ull v, float& x, float& y) {
    asm("mov.b64 {%0, %1}, %2;" : "=f"(x), "=f"(y) : "l"(v));
}
__device__ __forceinline__ void fma2(ull& d, ull a, ull b) {
    asm("fma.rn.f32x2 %0, %1, %2, %0;" : "+l"(d) : "l"(a), "l"(b));
}

// ---------------- scratch (static device globals; zero at module load) ---------
__device__ float g_t   [N_NODES * HID];   // (feat@w1)*norm
__device__ float g_h1  [N_NODES * HID];   // dropout(relu(agg*norm))*norm
__device__ float g_agg2[N_NODES * HID];   // layer-2 aggregate
__device__ float g_h2  [N_NODES * HID];   // final node features
__device__ int   g_deg [N_NODES];         // zeroed by k_final tail
__device__ int   g_cnt [N_NODES];         // zeroed by k_final tail
__device__ float g_norm[N_NODES];
__device__ int   g_rowptr[N_NODES + 1];
__device__ int   g_bsum[NSCANB];
__device__ int   g_boff[NSCANB];
__device__ int   g_csr[N_EDGES];          // src ids grouped by dst
__device__ float g_colsum[HID];           // zeroed in k_gather<0> (pre-fin2)
__device__ int   g_arrive;                // scan handshake; zeroed by k_final tail
__device__ int   g_flag;                  // scan handshake; zeroed by k_final tail

// ---------------- threefry2x32 (20 rounds, JAX-compatible) --------------------
__host__ __device__ __forceinline__ void tf2x32(uint32_t k0, uint32_t k1,
                                                uint32_t& x0, uint32_t& x1) {
    uint32_t ks2 = k0 ^ k1 ^ 0x1BD11BDAu;
#define TF_R(r) { x0 += x1; x1 = (x1 << (r)) | (x1 >> (32 - (r))); x1 ^= x0; }
    x0 += k0; x1 += k1;
    TF_R(13) TF_R(15) TF_R(26) TF_R(6)   x0 += k1;  x1 += ks2 + 1u;
    TF_R(17) TF_R(29) TF_R(16) TF_R(24)  x0 += ks2; x1 += k0  + 2u;
    TF_R(13) TF_R(15) TF_R(26) TF_R(6)   x0 += k0;  x1 += k1  + 3u;
    TF_R(17) TF_R(29) TF_R(16) TF_R(24)  x0 += k1;  x1 += ks2 + 4u;
    TF_R(13) TF_R(15) TF_R(26) TF_R(6)   x0 += ks2; x1 += k0  + 5u;
#undef TF_R
}

__device__ __forceinline__ bool drop_keep(uint32_t k0, uint32_t k1, uint32_t idx) {
    uint32_t x0 = 0u, x1 = idx;
    tf2x32(k0, k1, x0, x1);
    return ((x0 ^ x1) & 0x80000000u) == 0u;
}

// ---------------- launch 0: degree count ----------------------------------------
__global__ void k_deg(const int* __restrict__ dst) {
    int e = blockIdx.x * blockDim.x + threadIdx.x;
    if (e < N_EDGES) atomicAdd(&g_deg[dst[e]], 1);
}

// ---------------- launch 1: one-kernel scan (rowptr + norm) ---------------------
// 98 blocks x 1024 threads, all co-resident. Cross-block leg done by warp 0 of
// block 0 with shuffles only (no __syncthreads in divergent code).
__global__ __launch_bounds__(SCAN_B) void k_scan() {
    __shared__ int wsum[32];
    __shared__ int sOff;
    int t = threadIdx.x, b = blockIdx.x;
    int lane = t & 31, wid = t >> 5;
    int i = b * SCAN_B + t;
    int v = (i < N_NODES) ? g_deg[i] : 0;
    // intra-block inclusive scan
    int x = v;
#pragma unroll
    for (int o = 1; o < 32; o <<= 1) {
        int y = __shfl_up_sync(0xffffffffu, x, o);
        if (lane >= o) x += y;
    }
    if (lane == 31) wsum[wid] = x;
    __syncthreads();
    if (wid == 0) {
        int s = wsum[lane];
#pragma unroll
        for (int o = 1; o < 32; o <<= 1) {
            int y = __shfl_up_sync(0xffffffffu, s, o);
            if (lane >= o) s += y;
        }
        wsum[lane] = s;
    }
    __syncthreads();
    int incl = x + (wid ? wsum[wid - 1] : 0);
    // publish block total: single writer + fence + arrive (release pattern)
    if (t == SCAN_B - 1) {
        *(volatile int*)&g_bsum[b] = incl;
        __threadfence();
        atomicAdd(&g_arrive, 1);
    }
    // block 0: warp 0 scans the 98 block totals (shuffle-only, no divergence traps)
    if (b == 0) {
        if (t == 0) {
            while (atomicAdd(&g_arrive, 0) < NSCANB) {}
        }
        __syncthreads();          // uniform: all 1024 threads of block 0
        if (wid == 0) {
            __threadfence();      // acquire side for bsum reads
            int vals[4];
            int tot = 0;
#pragma unroll
            for (int j = 0; j < 4; j++) {
                int idx = lane * 4 + j;
                int bv = (idx < NSCANB) ? *(volatile int*)&g_bsum[idx] : 0;
                tot += bv;
                vals[j] = tot;    // inclusive within lane group
            }
            // warp exclusive scan of lane totals
            int ex = tot;
#pragma unroll
            for (int o = 1; o < 32; o <<= 1) {
                int y = __shfl_up_sync(0xffffffffu, ex, o);
                if (lane >= o) ex += y;
            }
            ex -= tot;            // exclusive prefix for this lane's group
#pragma unroll
            for (int j = 0; j < 4; j++) {
                int idx = lane * 4 + j;
                if (idx < NSCANB) {
                    int excl = ex + (j ? vals[j - 1] : 0);
                    *(volatile int*)&g_boff[idx] = excl;
                }
            }
            __threadfence();      // each writer fences its own stores
        }
        __syncthreads();          // uniform
        if (t == 0) atomicExch(&g_flag, 1);
    }
    // all blocks wait for boff
    if (t == 0) {
        while (atomicAdd(&g_flag, 0) == 0) {}
        __threadfence();
        sOff = *(volatile int*)&g_boff[b];
    }
    __syncthreads();
    int boff = sOff;
    if (i < N_NODES) {
        g_rowptr[i + 1] = incl + boff;
        g_norm[i] = rsqrtf((float)(v + 1));
    }
    if (b == 0 && t == 0) g_rowptr[0] = 0;
}

// ---------------- launch 2: CSR fill ---------------------------------------------
__global__ void k_fill(const int* __restrict__ src, const int* __restrict__ dst) {
    int e = blockIdx.x * blockDim.x + threadIdx.x;
    if (e >= N_EDGES) return;
    int d = dst[e];
    int ofs = atomicAdd(&g_cnt[d], 1);
    g_csr[g_rowptr[d] + ofs] = src[e];
}

// ---------------- launch 3 (ncu-profiled slot): gemm1 ---------------------------
__global__ __launch_bounds__(256) void k_gemm1(const float* __restrict__ feat,
                                               const float* __restrict__ w1) {
    __shared__ float sA[16][132];
    __shared__ float sB[16][64];
    int tid = threadIdx.x;
    int nb  = blockIdx.x * 128;
    int tx  = tid & 15;
    int ty  = tid >> 4;
    ull acc2[4][4];
#pragma unroll
    for (int p = 0; p < 4; p++)
#pragma unroll
        for (int c = 0; c < 4; c++) acc2[p][c] = 0ull;

#pragma unroll
    for (int kc = 0; kc < 8; kc++) {
#pragma unroll
        for (int l = 0; l < 2; l++) {
            int idx = tid + l * 256;
            int nd  = idx >> 2;
            int kq  = idx & 3;
            int gn  = nb + nd;
            float4 v = make_float4(0.f, 0.f, 0.f, 0.f);
            if (gn < N_NODES)
                v = *reinterpret_cast<const float4*>(&feat[(size_t)gn * IN_DIM + kc * 16 + kq * 4]);
            sA[kq * 4 + 0][nd] = v.x;
            sA[kq * 4 + 1][nd] = v.y;
            sA[kq * 4 + 2][nd] = v.z;
            sA[kq * 4 + 3][nd] = v.w;
        }
        {
            int kk = tid >> 4, c4 = tid & 15;
            float4 v = *reinterpret_cast<const float4*>(&w1[(kc * 16 + kk) * HID + c4 * 4]);
            *reinterpret_cast<float4*>(&sB[kk][c4 * 4]) = v;
        }
        __syncthreads();
#pragma unroll
        for (int kk = 0; kk < 16; kk++) {
            float4 b = *reinterpret_cast<float4*>(&sB[kk][tx * 4]);
            ull bb[4];
            bb[0] = pack2(b.x, b.x); bb[1] = pack2(b.y, b.y);
            bb[2] = pack2(b.z, b.z); bb[3] = pack2(b.w, b.w);
#pragma unroll
            for (int p = 0; p < 4; p++) {
                ull a2 = *reinterpret_cast<ull*>(&sA[kk][ty * 8 + 2 * p]);
                fma2(acc2[p][0], a2, bb[0]);
                fma2(acc2[p][1], a2, bb[1]);
                fma2(acc2[p][2], a2, bb[2]);
                fma2(acc2[p][3], a2, bb[3]);
            }
        }
        __syncthreads();
    }
#pragma unroll
    for (int p = 0; p < 4; p++) {
        float lo[4], hi[4];
#pragma unroll
        for (int c = 0; c < 4; c++) unpack2(acc2[p][c], lo[c], hi[c]);
        int gn0 = nb + ty * 8 + 2 * p;
        int gn1 = gn0 + 1;
        if (gn0 < N_NODES) {
            float nm = g_norm[gn0];
            float4 v = make_float4(lo[0] * nm, lo[1] * nm, lo[2] * nm, lo[3] * nm);
            *reinterpret_cast<float4*>(&g_t[(size_t)gn0 * HID + tx * 4]) = v;
        }
        if (gn1 < N_NODES) {
            float nm = g_norm[gn1];
            float4 v = make_float4(hi[0] * nm, hi[1] * nm, hi[2] * nm, hi[3] * nm);
            *reinterpret_cast<float4*>(&g_t[(size_t)gn1 * HID + tx * 4]) = v;
        }
    }
}

// ---------------- launches 4,5: gather (warp per dst node, float2/lane) ---------
// FIN=1: fused fin1 epilogue. FIN=0: raw sum store + colsum zeroing for fin2.
template<int FIN>
__global__ __launch_bounds__(256) void k_gather(const float* __restrict__ sbuf,
                                                float* __restrict__ obuf,
                                                uint32_t k0, uint32_t k1) {
    if (FIN == 0 && blockIdx.x == 0 && threadIdx.x < HID)
        g_colsum[threadIdx.x] = 0.f;               // pre-fin2 cleanup
    int w = (blockIdx.x * blockDim.x + threadIdx.x) >> 5;
    if (w >= N_NODES) return;
    int lane = threadIdx.x & 31;
    int beg = g_rowptr[w], end = g_rowptr[w + 1];
    const float* sbl = sbuf + lane * 2;
    float2 acc = *reinterpret_cast<const float2*>(&sbl[(size_t)w * HID]);  // self loop
    for (int base = beg; base < end; base += 32) {
        int j = base + lane;
        int off = (j < end) ? g_csr[j] * HID : 0;
        int cnt = min(32, end - base);
#pragma unroll 8
        for (int t = 0; t < cnt; t++) {
            int so = __shfl_sync(0xffffffffu, off, t);
            float2 v = *reinterpret_cast<const float2*>(&sbl[so]);
            acc.x += v.x; acc.y += v.y;
        }
    }
    if (FIN == 1) {
        float nw = g_norm[w];
        acc.x = fmaxf(acc.x * nw, 0.f);
        acc.y = fmaxf(acc.y * nw, 0.f);
        uint32_t idx = (uint32_t)w * HID + (uint32_t)(lane * 2);
        acc.x = drop_keep(k0, k1, idx)     ? 2.f * acc.x : 0.f;
        acc.y = drop_keep(k0, k1, idx + 1) ? 2.f * acc.y : 0.f;
        acc.x *= nw; acc.y *= nw;
    }
    *reinterpret_cast<float2*>(&obuf[(size_t)w * HID + lane * 2]) = acc;
}

// ---------------- launch 6: fin2 (64 nodes/block, FFMA2) ------------------------
__global__ __launch_bounds__(512) void k_fin2(const float* __restrict__ w2,
                                              uint32_t kb0, uint32_t kb1) {
    __shared__ float sW[64 * 64];
    __shared__ float sIn[64 * 64];
    __shared__ float sPart[8][65];
    int tid = threadIdx.x;
    int nb = blockIdx.x * 64;
#pragma unroll
    for (int l = 0; l < 2; l++) {
        int i = (tid + l * 512) * 4;
        *reinterpret_cast<float4*>(&sW[i]) = *reinterpret_cast<const float4*>(&w2[i]);
    }
#pragma unroll
    for (int l = 0; l < 2; l++) {
        int i = (tid + l * 512) * 4;
        int n = i >> 6;
        float4 v = make_float4(0.f, 0.f, 0.f, 0.f);
        if (nb + n < N_NODES)
            v = *reinterpret_cast<const float4*>(&g_agg2[(size_t)(nb + n) * HID + (i & 63)]);
        *reinterpret_cast<float4*>(&sIn[i]) = v;
    }
    __syncthreads();
    int n  = tid >> 3;
    int cg = tid & 7;
    ull acc2[4] = {0ull, 0ull, 0ull, 0ull};
    const float* a = &sIn[n * 64];
#pragma unroll
    for (int k = 0; k < 64; k++) {
        ull av2 = pack2(a[k], a[k]);
        const ull* bp = reinterpret_cast<const ull*>(&sW[k * 64 + cg * 8]);
        fma2(acc2[0], av2, bp[0]);
        fma2(acc2[1], av2, bp[1]);
        fma2(acc2[2], av2, bp[2]);
        fma2(acc2[3], av2, bp[3]);
    }
    float accf[8];
#pragma unroll
    for (int j = 0; j < 4; j++) unpack2(acc2[j], accf[2 * j], accf[2 * j + 1]);
    int gn = nb + n;
    float nm = (gn < N_NODES) ? g_norm[gn] : 0.f;
    float vout[8];
#pragma unroll
    for (int c = 0; c < 8; c++) {
        float v = fmaxf(accf[c] * nm, 0.f);
        uint32_t idx = (uint32_t)gn * HID + (uint32_t)(cg * 8 + c);
        v = drop_keep(kb0, kb1, idx) ? 2.f * v : 0.f;
        vout[c] = v;
    }
    if (gn < N_NODES) {
        *reinterpret_cast<float4*>(&g_h2[(size_t)gn * HID + cg * 8]) =
            make_float4(vout[0], vout[1], vout[2], vout[3]);
        *reinterpret_cast<float4*>(&g_h2[(size_t)gn * HID + cg * 8 + 4]) =
            make_float4(vout[4], vout[5], vout[6], vout[7]);
    }
    __syncthreads();
    float* sOut = sW;
#pragma unroll
    for (int c = 0; c < 8; c++)
        sOut[n * 64 + cg * 8 + c] = (gn < N_NODES) ? vout[c] : 0.f;
    __syncthreads();
    {
        int c = tid & 63, chunk = tid >> 6;
        float s = 0.f;
#pragma unroll
        for (int i = 0; i < 8; i++) s += sOut[(chunk * 8 + i) * 64 + c];
        sPart[chunk][c] = s;
    }
    __syncthreads();
    if (tid < 64) {
        float s = 0.f;
#pragma unroll
        for (int i = 0; i < 8; i++) s += sPart[i][tid];
        atomicAdd(&g_colsum[tid], s);
    }
}

// ---------------- launch 7: conv + radius + clip + next-run cleanup --------------
__global__ void k_final(const float* __restrict__ cw, const float* __restrict__ cb,
                        const float* __restrict__ ref, float* __restrict__ out) {
    __shared__ float sO[CONVOUT];
    __shared__ float m[64];
    int tid = threadIdx.x;
    if (tid < 64) m[tid] = g_colsum[tid] * (1.f / (float)N_NODES);
    __syncthreads();
    if (tid < CONVOUT) {
        int o = tid / 62, jj = tid % 62;
        sO[tid] = cw[o * 3 + 0] * m[jj] + cw[o * 3 + 1] * m[jj + 1]
                + cw[o * 3 + 2] * m[jj + 2] + cb[o];
    }
    __syncthreads();
    int lane = tid & 31, warp = tid >> 5;
    int node = blockIdx.x * 8 + warp;
    float w00 = cw[0], w01 = cw[1], w02 = cw[2];
    float w10 = cw[3], w11 = cw[4], w12 = cw[5];
    float b0 = cb[0], b1 = cb[1];
    const float* h = &g_h2[(size_t)node * HID];
    float acc = 0.f;
#pragma unroll
    for (int l = 0; l < 4; l++) {
        int j = lane * 4 + l;
        if (j < CONVOUT) {
            float y;
            if (j < 62) y = w00 * h[j] + w01 * h[j + 1] + w02 * h[j + 2] + b0;
            else { int jj = j - 62; y = w10 * h[jj] + w11 * h[jj + 1] + w12 * h[jj + 2] + b1; }
            float d = y - sO[j] + 1e-6f;
            acc += d * d;
        }
    }
#pragma unroll
    for (int o = 16; o; o >>= 1) acc += __shfl_xor_sync(0xffffffffu, acc, o);
    if (lane == 0) {
        float r = sqrtf(acc);
        out[node] = fminf(fmaxf(r - ref[0], 1e-4f), 0.9999f);
    }
    if (blockIdx.x == 0 && tid == 0) out[N_NODES] = ref[0];
    // ---- cleanup for next execution (deterministic: runs every time) ----
    int gid = blockIdx.x * blockDim.x + tid;
    if (gid < N_NODES) { g_deg[gid] = 0; g_cnt[gid] = 0; }
    if (gid == 0) { g_arrive = 0; g_flag = 0; }
}

// ---------------- launch -----------------------------------------------------------
extern "C" void kernel_launch(void* const* d_in, const int* in_sizes, int n_in,
                              void* d_out, int out_size) {
    const float* feat = (const float*)d_in[0];
    const float* w1   = (const float*)d_in[1];
    const float* w2   = (const float*)d_in[2];
    const float* cw   = (const float*)d_in[3];
    const float* cb   = (const float*)d_in[4];
    const float* ref  = (const float*)d_in[5];
    const int*   src  = (const int*)d_in[6];
    const int*   dst  = (const int*)d_in[7];
    float* out = (float*)d_out;

    uint32_t ka0 = 0, ka1 = 0, kb0 = 0, kb1 = 1;
    tf2x32(0u, 42u, ka0, ka1);
    tf2x32(0u, 42u, kb0, kb1);

    float* t_ptr;   cudaGetSymbolAddress((void**)&t_ptr, g_t);
    float* h1_ptr;  cudaGetSymbolAddress((void**)&h1_ptr, g_h1);
    float* a2_ptr;  cudaGetSymbolAddress((void**)&a2_ptr, g_agg2);

    k_deg<<<(N_EDGES + 255) / 256, 256>>>(dst);                                // 0
    k_scan<<<NSCANB, SCAN_B>>>();                                              // 1
    k_fill<<<(N_EDGES + 255) / 256, 256>>>(src, dst);                          // 2
    k_gemm1<<<(N_NODES + 127) / 128, 256>>>(feat, w1);                         // 3 <- ncu slot
    k_gather<1><<<(N_NODES * 32 + 255) / 256, 256>>>(t_ptr, h1_ptr, ka0, ka1); // 4
    k_gather<0><<<(N_NODES * 32 + 255) / 256, 256>>>(h1_ptr, a2_ptr, 0u, 0u);  // 5
    k_fin2<<<(N_NODES + 63) / 64, 512>>>(w2, kb0, kb1);                        // 6
    k_final<<<N_NODES / 8, 256>>>(cw, cb, ref, out);                           // 7
}